// round 3
// baseline (speedup 1.0000x reference)
#include <cuda_runtime.h>

#define D        64
#define HH       64
#define D_INPUT  2145
#define PATHS_PER_BLOCK 128   // 64 threads x 2 paths
#define TPB      64
#define OBS_PAD  68           // 68 floats = 272B = 17*16 -> 16B-aligned rows, conflict-free LDS.128

typedef unsigned long long ull;

__device__ float g_wt[HH][D * D];   // upper-triangular, zero below diagonal
__device__ float g_wl[HH][D];       // linear weights

// ---------------------------------------------------------------------------
// packed f32x2 helpers (sm_103a)
// ---------------------------------------------------------------------------
__device__ __forceinline__ ull f2fma(ull a, ull b, ull c) {
    ull d;
    asm("fma.rn.f32x2 %0, %1, %2, %3;" : "=l"(d) : "l"(a), "l"(b), "l"(c));
    return d;
}
__device__ __forceinline__ ull f2add(ull a, ull b) {
    ull d;
    asm("add.rn.f32x2 %0, %1, %2;" : "=l"(d) : "l"(a), "l"(b));
    return d;
}
__device__ __forceinline__ ull dup_lo(ull p) { return (p & 0xffffffffull) | (p << 32); }
__device__ __forceinline__ ull dup_hi(ull p) { return (p >> 32) | (p & 0xffffffff00000000ull); }
__device__ __forceinline__ float hsum(ull p) {
    float lo = __uint_as_float((unsigned)(p & 0xffffffffull));
    float hi = __uint_as_float((unsigned)(p >> 32));
    return lo + hi;
}

// ---------------------------------------------------------------------------
// Prep: unpack packed-triangular weights into regular [i][j] rows, zero below
// diagonal. weights[h][64 + base(i) + (j-i)], base(i) = i*64 - i*(i-1)/2.
// ---------------------------------------------------------------------------
__global__ void prep_kernel(const float* __restrict__ w) {
    const int h = blockIdx.x;
    const float* wh = w + (size_t)h * D_INPUT;
    for (int idx = threadIdx.x; idx < D * D; idx += blockDim.x) {
        const int i = idx >> 6;
        const int j = idx & 63;
        float v = 0.0f;
        if (j >= i) {
            const int base = i * D - (i * (i - 1)) / 2;
            v = wh[D + base + (j - i)];
        }
        g_wt[h][idx] = v;
    }
    if (threadIdx.x < D) g_wl[h][threadIdx.x] = wh[threadIdx.x];
}

// ---------------------------------------------------------------------------
// Main kernel: block = (128-path tile, h); 64 threads; thread owns paths
// (pbase+tid, pbase+64+tid). Weights stream once per warp as LDS.128 broadcast
// and feed both paths; all math packed f32x2.
// ---------------------------------------------------------------------------
extern __shared__ float smem[];

__global__ __launch_bounds__(TPB)
void vf_kernel(const float* __restrict__ obs,
               const float* __restrict__ biases,
               float* __restrict__ out) {
    const int h     = blockIdx.y;
    const int pbase = blockIdx.x * PATHS_PER_BLOCK;
    const int tid   = threadIdx.x;

    float* s_w   = smem;                    // 4096 floats (16B-aligned rows of 256B)
    float* s_wl  = smem + D * D;            // 64 floats
    float* s_obs = smem + D * D + D;        // 128 rows x OBS_PAD (base 4160 floats: 16B-aligned)

    // --- Stage weights: 1024 float4, 16/thread; + linear weights
    {
        const float4* gw4 = reinterpret_cast<const float4*>(&g_wt[h][0]);
        float4*       sw4 = reinterpret_cast<float4*>(s_w);
        #pragma unroll
        for (int k = 0; k < 16; k++) sw4[tid + TPB * k] = gw4[tid + TPB * k];
        if (tid < D / 4)
            reinterpret_cast<float4*>(s_wl)[tid] =
                reinterpret_cast<const float4*>(&g_wl[h][0])[tid];
    }

    // --- Stage all 128 path rows (both halves), coalesced LDG.128 + STS.128
    {
        #pragma unroll
        for (int k = 0; k < 32; k++) {
            const int f = tid + TPB * k;
            const int p = f >> 4;     // 0..127
            const int q = f & 15;
            const float4 v = reinterpret_cast<const float4*>(obs)
                [(size_t)(pbase + p) * (HH * D / 4) + (size_t)h * (D / 4) + q];
            *reinterpret_cast<float4*>(&s_obs[p * OBS_PAD + 4 * q]) = v;
        }
    }
    __syncthreads();

    // --- Fill both o-vectors as packed pairs (LDS.128, conflict-free)
    ull oA[D / 2], oB[D / 2];
    {
        const ulonglong2* rowA = reinterpret_cast<const ulonglong2*>(s_obs + tid * OBS_PAD);
        const ulonglong2* rowB = reinterpret_cast<const ulonglong2*>(s_obs + (tid + 64) * OBS_PAD);
        #pragma unroll
        for (int m = 0; m < D / 4; m++) {
            const ulonglong2 a = rowA[m];
            const ulonglong2 b = rowB[m];
            oA[2 * m] = a.x; oA[2 * m + 1] = a.y;
            oB[2 * m] = b.x; oB[2 * m + 1] = b.y;
        }
    }

    // --- Linear term (packed)
    ull accA = 0ull, accB = 0ull;
    {
        const ulonglong2* wl2 = reinterpret_cast<const ulonglong2*>(s_wl);
        #pragma unroll
        for (int m = 0; m < D / 4; m++) {
            const ulonglong2 w = wl2[m];
            accA = f2fma(w.x, oA[2 * m],     accA);
            accB = f2fma(w.x, oB[2 * m],     accB);
            accA = f2fma(w.y, oA[2 * m + 1], accA);
            accB = f2fma(w.y, oB[2 * m + 1], accB);
        }
    }

    // --- Triangular quadratic term; rows start float4-aligned, zeros pad below diag
    #pragma unroll
    for (int i = 0; i < D; i++) {
        const int j4s = i >> 2;
        const ulonglong2* wrow = reinterpret_cast<const ulonglong2*>(s_w + i * D);
        ull rA0 = 0ull, rA1 = 0ull, rB0 = 0ull, rB1 = 0ull;
        #pragma unroll
        for (int j4 = j4s; j4 < 16; j4++) {
            const ulonglong2 w = wrow[j4];       // one LDS.128 broadcast, two f32x2 operands
            rA0 = f2fma(w.x, oA[2 * j4],     rA0);
            rB0 = f2fma(w.x, oB[2 * j4],     rB0);
            rA1 = f2fma(w.y, oA[2 * j4 + 1], rA1);
            rB1 = f2fma(w.y, oB[2 * j4 + 1], rB1);
        }
        const ull rAt = f2add(rA0, rA1);
        const ull rBt = f2add(rB0, rB1);
        const ull oiA = (i & 1) ? dup_hi(oA[i >> 1]) : dup_lo(oA[i >> 1]);
        const ull oiB = (i & 1) ? dup_hi(oB[i >> 1]) : dup_lo(oB[i >> 1]);
        accA = f2fma(oiA, rAt, accA);
        accB = f2fma(oiB, rBt, accB);
    }

    const float b = biases[h];
    out[(size_t)(pbase + tid)      * HH + h] = hsum(accA) + b;
    out[(size_t)(pbase + 64 + tid) * HH + h] = hsum(accB) + b;
}

// ---------------------------------------------------------------------------
extern "C" void kernel_launch(void* const* d_in, const int* in_sizes, int n_in,
                              void* d_out, int out_size) {
    const float* obs = (const float*)d_in[0];
    const float* w   = (const float*)d_in[1];
    const float* b   = (const float*)d_in[2];
    float* out       = (float*)d_out;

    const int N = in_sizes[0] / (HH * D);   // 1024

    prep_kernel<<<HH, 512>>>(w);

    const int smem_bytes = (D * D + D + PATHS_PER_BLOCK * OBS_PAD) * (int)sizeof(float); // ~51.5 KB
    cudaFuncSetAttribute(vf_kernel, cudaFuncAttributeMaxDynamicSharedMemorySize, smem_bytes);

    dim3 grid(N / PATHS_PER_BLOCK, HH);     // (8, 64) = 512 blocks
    vf_kernel<<<grid, TPB, smem_bytes>>>(obs, b, out);
}